// round 16
// baseline (speedup 1.0000x reference)
#include <cuda_runtime.h>

typedef unsigned long long u64;

// ci-pair-interleaved x: g_xi[b][d][h][pair][2w + par], par = ci&1
// (8 * 24 * 24 * 8 * 48 floats = 7.08 MB). One LDG.128 = two f32x2 operands.
__device__ __align__(16) float g_xi[8 * 24 * 24 * 384];

// ---------------------------------------------------------------------------
// Pre-pass: build g_xi. 864 blocks x 512 threads = 442368 threads, exactly
// one float4 of g_xi per thread; writes fully coalesced.
// ---------------------------------------------------------------------------
__global__ __launch_bounds__(512)
void pre_kernel(const float* __restrict__ x) {
    int g = blockIdx.x * 512 + threadIdx.x;          // 0..442367
    int wq = g % 12;                                 // float4 within pair-row
    int t = g / 12;
    int pair = t & 7;  t >>= 3;
    int h = t % 24;    t /= 24;
    int d = t % 24;
    int b = t / 24;
    const float* r0 =
        x + (((size_t)(b * 16 + 2 * pair) * 24 + d) * 24 + h) * 24 + 2 * wq;
    float2 a = __ldg(reinterpret_cast<const float2*>(r0));
    float2 c = __ldg(reinterpret_cast<const float2*>(r0 + 13824));
    reinterpret_cast<float4*>(g_xi)[g] = make_float4(a.x, c.x, a.y, c.y);
}

__device__ __forceinline__ void fma2(u64& d, u64 a, u64 b) {
    asm("fma.rn.f32x2 %0, %1, %2, %0;" : "+l"(d) : "l"(a), "l"(b));
}

// Separable tap-set fold, fully unrolled, compile-time indices only.
// T(0)={1,2}, T(1)={0,1,2}, T(2)={0}  (from z = 2i-1+k, z-offset in [0,3])
__device__ __forceinline__ void fold27(const float* __restrict__ a, float sc,
                                       float* __restrict__ o) {
    float c[27];
#pragma unroll
    for (int j = 0; j < 9; ++j) {
        float i0 = a[3 * j], i1 = a[3 * j + 1], i2 = a[3 * j + 2];
        float t = i1 + i2;
        c[3 * j + 0] = t; c[3 * j + 1] = t + i0; c[3 * j + 2] = i0;
    }
    float d[27];
#pragma unroll
    for (int kd = 0; kd < 3; ++kd)
#pragma unroll
        for (int rw = 0; rw < 3; ++rw) {
            float r0 = c[(3 * kd + 0) * 3 + rw];
            float r1 = c[(3 * kd + 1) * 3 + rw];
            float r2 = c[(3 * kd + 2) * 3 + rw];
            float t = r1 + r2;
            d[(kd * 3 + 0) * 3 + rw] = t;
            d[(kd * 3 + 1) * 3 + rw] = t + r0;
            d[(kd * 3 + 2) * 3 + rw] = r0;
        }
#pragma unroll
    for (int rh = 0; rh < 3; ++rh)
#pragma unroll
        for (int rw = 0; rw < 3; ++rw) {
            float r0 = d[(0 * 3 + rh) * 3 + rw];
            float r1 = d[(1 * 3 + rh) * 3 + rw];
            float r2 = d[(2 * 3 + rh) * 3 + rw];
            float t = r1 + r2;
            o[(0 * 3 + rh) * 3 + rw] = t * sc;
            o[(1 * 3 + rh) * 3 + rw] = (t + r0) * sc;
            o[(2 * 3 + rh) * 3 + rw] = r0 * sc;
        }
}

// ---------------------------------------------------------------------------
// Main: 296 blocks x 256 threads, 2 blocks/SM. NO smem x: compute warps
// __ldg their ci-pair rows of g_xi directly (each LDG.128 = 2 f32x2 pairs,
// 12-wide MLP per row; smem is only 27.6 KB so L1D ~200 KB caches x tiles).
// Weights register-pinned via in-kernel fold (R12). Per warp per tile:
// 108 LDG + 99 fma2 + ~50 misc -- half of R12's instruction stream.
// Block bid does tiles bid + it*296 (nt = 4 for bid<80 else 3).
// smem union: fold scratch (8x864 floats) first, then red (8x352) forever.
// ---------------------------------------------------------------------------
__global__ __launch_bounds__(256, 2)
void conv_fused_kernel(const float* __restrict__ wsrc,
                       const float* __restrict__ bias,
                       const float* __restrict__ gamma,
                       const float* __restrict__ beta,
                       const float* __restrict__ mean,
                       const float* __restrict__ var,
                       float* __restrict__ out) {
    __shared__ __align__(16) float smem_u[8 * 864];   // 27648 B

    const int tid  = threadIdx.x;
    const int lane = tid & 31;   // co
    const int wid  = tid >> 5;   // ci pair
    const int bid  = blockIdx.x;

    const float scale = __ldg(&gamma[lane]) * rsqrtf(__ldg(&var[lane]) + 1e-5f);
    const float cb = __ldg(&bias[lane]) * scale + __ldg(&beta[lane])
                   - __ldg(&mean[lane]) * scale;
    const float sc64 = scale * (1.f / 64.f);

    // ====== in-kernel weight fold -> 27 register-pinned f32x2 per warp ======
    u64 wr[27];
    {
        float* scr = smem_u + wid * 864;   // 3456 B per warp
        float o0[27], o1[27];
#pragma unroll 1
        for (int ph = 0; ph < 2; ++ph) {   // ci = 2*wid + ph
            const float4* src = reinterpret_cast<const float4*>(
                wsrc + (size_t)(2 * wid + ph) * 864);
            float4* dst = reinterpret_cast<float4*>(scr);
#pragma unroll
            for (int k = 0; k < 7; ++k) {
                int i = lane + k * 32;
                if (i < 216) dst[i] = __ldg(src + i);
            }
            __syncwarp();
            float a[27];
            const float* ap = scr + lane * 27;   // stride 27 vs 32 banks: clean
#pragma unroll
            for (int k = 0; k < 27; ++k) a[k] = ap[k];
            fold27(a, sc64, ph ? o1 : o0);
            __syncwarp();
        }
#pragma unroll
        for (int r = 0; r < 27; ++r)
            asm("mov.b64 %0, {%1, %2};" : "=l"(wr[r]) : "f"(o0[r]), "f"(o1[r]));
    }
    __syncthreads();   // scratch now becomes the reduction buffer

    float* red = smem_u;             // red[wid][ow*32+lane], 8*352 floats
    const int nt = (bid < 80) ? 4 : 3;   // 80*4 + 216*3 = 968 tiles

#pragma unroll 1
    for (int it = 0; it < nt; ++it) {
        const int gw = bid + it * 296;
        const int b = gw / 121, rem = gw - b * 121;
        const int od = rem / 11, oh = rem - od * 11;

        // this warp's ci-pair base row in g_xi: [b][2od][2oh][wid][48]
        const u64* base = reinterpret_cast<const u64*>(g_xi) +
            ((((size_t)b * 24 + 2 * od) * 24 + 2 * oh) * 8 + wid) * 24;
        // row (rd, rh): + rd*4608 + rh*192 (u64 units)

        u64 acc[11];
#pragma unroll
        for (int i = 0; i < 11; ++i) acc[i] = 0ull;

#pragma unroll
        for (int rr = 0; rr < 9; ++rr) {
            const int rd = rr / 3, rh = rr - rd * 3;
            const longlong2* rp = reinterpret_cast<const longlong2*>(
                base + rd * 4608 + rh * 192);
            const u64 w0 = wr[rr * 3 + 0];
            const u64 w1 = wr[rr * 3 + 1];
            const u64 w2 = wr[rr * 3 + 2];

            // half 1: x positions 0..13 (7 hoisted LDG.128)
            u64 xv[14];
#pragma unroll
            for (int k = 0; k < 7; ++k) {
                longlong2 t = __ldg(rp + k);
                xv[2 * k] = (u64)t.x; xv[2 * k + 1] = (u64)t.y;
            }
#pragma unroll
            for (int ow = 0; ow < 6; ++ow) {
                fma2(acc[ow], w0, xv[2 * ow]);
                fma2(acc[ow], w1, xv[2 * ow + 1]);
                fma2(acc[ow], w2, xv[2 * ow + 2]);
            }
            // half 2: x positions 14..23 (5 hoisted LDG.128)
            u64 xu[10];
#pragma unroll
            for (int k = 0; k < 5; ++k) {
                longlong2 t = __ldg(rp + 7 + k);
                xu[2 * k] = (u64)t.x; xu[2 * k + 1] = (u64)t.y;
            }
            fma2(acc[6], w0, xv[12]);
            fma2(acc[6], w1, xv[13]);
            fma2(acc[6], w2, xu[0]);
#pragma unroll
            for (int ow = 7; ow < 11; ++ow) {
                fma2(acc[ow], w0, xu[2 * ow - 14]);
                fma2(acc[ow], w1, xu[2 * ow - 13]);
                fma2(acc[ow], w2, xu[2 * ow - 12]);
            }
        }

        // ---- cross-warp reduce ----
        float* rw_ = red + wid * 352;
#pragma unroll
        for (int ow = 0; ow < 11; ++ow) {
            float lo, hi;
            asm("mov.b64 {%0, %1}, %2;" : "=f"(lo), "=f"(hi) : "l"(acc[ow]));
            rw_[ow * 32 + lane] = lo + hi;
        }
        __syncthreads();   // red ready

        // ---- store (co = lane since 256 % 32 == 0) ----
        if (tid < 96) {
            int j = tid + 256;
            float s1 = cb;
#pragma unroll
            for (int w = 0; w < 8; ++w) s1 += red[w * 352 + j];
            out[((size_t)(b * 32 + lane)) * 1331 + od * 121 + oh * 11 + (j >> 5)] = s1;
        }
        {
            int j0 = (tid < 352) ? tid : 0;
            float s0 = cb;
#pragma unroll
            for (int w = 0; w < 8; ++w) s0 += red[w * 352 + j0];
            if (tid < 352)
                out[((size_t)(b * 32 + lane)) * 1331 + od * 121 + oh * 11 + (tid >> 5)] = s0;
        }
        __syncthreads();   // red reads done before next tile's writes
    }
}

extern "C" void kernel_launch(void* const* d_in, const int* in_sizes, int n_in,
                              void* d_out, int out_size) {
    const float* x     = (const float*)d_in[0];
    const float* w     = (const float*)d_in[1];
    const float* bias  = (const float*)d_in[2];
    const float* gamma = (const float*)d_in[3];
    const float* beta  = (const float*)d_in[4];
    const float* mean  = (const float*)d_in[5];
    const float* var   = (const float*)d_in[6];
    float* out = (float*)d_out;

    pre_kernel<<<864, 512>>>(x);
    conv_fused_kernel<<<296, 256>>>(w, bias, gamma, beta, mean, var, out);
}

// round 17
// speedup vs baseline: 1.6224x; 1.6224x over previous
#include <cuda_runtime.h>

typedef unsigned long long u64;

__device__ __forceinline__ void fma2(u64& d, u64 a, u64 b) {
    asm("fma.rn.f32x2 %0, %1, %2, %0;" : "+l"(d) : "l"(a), "l"(b));
}

// Separable tap-set fold, fully unrolled, compile-time indices only.
// T(0)={1,2}, T(1)={0,1,2}, T(2)={0}  (from z = 2i-1+k, z-offset in [0,3])
__device__ __forceinline__ void fold27(const float* __restrict__ a, float sc,
                                       float* __restrict__ o) {
    float c[27];
#pragma unroll
    for (int j = 0; j < 9; ++j) {
        float i0 = a[3 * j], i1 = a[3 * j + 1], i2 = a[3 * j + 2];
        float t = i1 + i2;
        c[3 * j + 0] = t; c[3 * j + 1] = t + i0; c[3 * j + 2] = i0;
    }
    float d[27];
#pragma unroll
    for (int kd = 0; kd < 3; ++kd)
#pragma unroll
        for (int rw = 0; rw < 3; ++rw) {
            float r0 = c[(3 * kd + 0) * 3 + rw];
            float r1 = c[(3 * kd + 1) * 3 + rw];
            float r2 = c[(3 * kd + 2) * 3 + rw];
            float t = r1 + r2;
            d[(kd * 3 + 0) * 3 + rw] = t;
            d[(kd * 3 + 1) * 3 + rw] = t + r0;
            d[(kd * 3 + 2) * 3 + rw] = r0;
        }
#pragma unroll
    for (int rh = 0; rh < 3; ++rh)
#pragma unroll
        for (int rw = 0; rw < 3; ++rw) {
            float r0 = d[(0 * 3 + rh) * 3 + rw];
            float r1 = d[(1 * 3 + rh) * 3 + rw];
            float r2 = d[(2 * 3 + rh) * 3 + rw];
            float t = r1 + r2;
            o[(0 * 3 + rh) * 3 + rw] = t * sc;
            o[(1 * 3 + rh) * 3 + rw] = (t + r0) * sc;
            o[(2 * 3 + rh) * 3 + rw] = r0 * sc;
        }
}

// ---------------------------------------------------------------------------
// Single fused kernel (R12 loop + single-barrier pipeline). 296 blocks x 256
// threads, 2 blocks/SM. Weights folded in-kernel into 27 register-pinned
// f32x2 per warp (ci pair = wid). x staged ci-pair-interleaved into double-
// buffered smem by block-wide LDG.128 one tile ahead (the prefetch engine).
// red double-buffered -> ONE __syncthreads per tile; the reduce+store of
// tile it overlaps tile it+1's compute issue.
// Block bid does tiles bid + it*296 (nt = 4 for bid < 80 else 3).
// ---------------------------------------------------------------------------
__global__ __launch_bounds__(256, 2)
void conv_fused_kernel(const float* __restrict__ x,
                       const float* __restrict__ wsrc,
                       const float* __restrict__ bias,
                       const float* __restrict__ gamma,
                       const float* __restrict__ beta,
                       const float* __restrict__ mean,
                       const float* __restrict__ var,
                       float* __restrict__ out) {
    extern __shared__ __align__(16) char sm[];
    u64*   xs  = reinterpret_cast<u64*>(sm);             // 2*1728 u64 = 27648 B
    float* red = reinterpret_cast<float*>(sm + 27648);   // 2*2816 f   = 22528 B

    const int tid  = threadIdx.x;
    const int lane = tid & 31;   // co
    const int wid  = tid >> 5;   // ci pair
    const int bid  = blockIdx.x;

    const float scale = __ldg(&gamma[lane]) * rsqrtf(__ldg(&var[lane]) + 1e-5f);
    const float cb = __ldg(&bias[lane]) * scale + __ldg(&beta[lane])
                   - __ldg(&mean[lane]) * scale;
    const float sc64 = scale * (1.f / 64.f);

    // ====== in-kernel weight fold -> 27 register-pinned f32x2 per warp ======
    u64 wr[27];
    {
        float* scr = reinterpret_cast<float*>(xs) + wid * 864;   // 3456 B/warp
        float o0[27], o1[27];
#pragma unroll 1
        for (int ph = 0; ph < 2; ++ph) {   // ci = 2*wid + ph
            const float4* src = reinterpret_cast<const float4*>(
                wsrc + (size_t)(2 * wid + ph) * 864);
            float4* dst = reinterpret_cast<float4*>(scr);
#pragma unroll
            for (int k = 0; k < 7; ++k) {
                int i = lane + k * 32;
                if (i < 216) dst[i] = __ldg(src + i);
            }
            __syncwarp();
            float a[27];
            const float* ap = scr + lane * 27;   // stride 27 vs 32 banks: clean
#pragma unroll
            for (int k = 0; k < 27; ++k) a[k] = ap[k];
            fold27(a, sc64, ph ? o1 : o0);
            __syncwarp();
        }
#pragma unroll
        for (int r = 0; r < 27; ++r)
            asm("mov.b64 %0, {%1, %2};" : "=l"(wr[r]) : "f"(o0[r]), "f"(o1[r]));
    }
    __syncthreads();   // all fold reads of the xs scratch done

    // ====== staging task decode (hoisted; 432 tasks per tile) ======
    const int p0  = tid / 54, u0 = tid - p0 * 54;
    const int rr0 = u0 / 6,  q0 = u0 - rr0 * 6;
    const int so0 = 2 * p0 * 13824 + (rr0 / 3) * 576 + (rr0 % 3) * 24 + 4 * q0;
    const int df0 = (p0 * 9 + rr0) * 12 + 2 * q0;      // float4 index in xs buf

    const bool h1 = (tid < 176);
    const int t1  = tid + 256;
    const int p1  = t1 / 54, u1 = t1 - p1 * 54;
    const int rr1 = u1 / 6,  q1 = u1 - rr1 * 6;
    const int so1 = 2 * p1 * 13824 + (rr1 / 3) * 576 + (rr1 % 3) * 24 + 4 * q1;
    const int df1 = (p1 * 9 + rr1) * 12 + 2 * q1;

    const int nt = (bid < 80) ? 4 : 3;   // 80*4 + 216*3 = 968 tiles

    // ====== prologue: stage tile 0 ======
    {
        int b = bid / 121, rem = bid - b * 121;
        const float* xb = x + (size_t)b * 221184 + 2 * (rem / 11) * 576 + 2 * (rem % 11) * 24;
        float4 A0 = __ldg(reinterpret_cast<const float4*>(xb + so0));
        float4 B0 = __ldg(reinterpret_cast<const float4*>(xb + so0 + 13824));
        float4* d = reinterpret_cast<float4*>(xs);
        d[df0]     = make_float4(A0.x, B0.x, A0.y, B0.y);
        d[df0 + 1] = make_float4(A0.z, B0.z, A0.w, B0.w);
        if (h1) {
            float4 A1 = __ldg(reinterpret_cast<const float4*>(xb + so1));
            float4 B1 = __ldg(reinterpret_cast<const float4*>(xb + so1 + 13824));
            d[df1]     = make_float4(A1.x, B1.x, A1.y, B1.y);
            d[df1 + 1] = make_float4(A1.z, B1.z, A1.w, B1.w);
        }
    }
    __syncthreads();

    // ====== main loop: ONE barrier per tile ======
#pragma unroll 1
    for (int it = 0; it < nt; ++it) {
        const int gw = bid + it * 296;
        const int b = gw / 121, rem = gw - b * 121;
        const int od = rem / 11, oh = rem - od * 11;

        // issue next tile's global loads (latency hidden under compute)
        const bool more = (it + 1) < nt;
        float4 A0, B0, A1, B1;
        if (more) {
            int gn = gw + 296;
            int bn = gn / 121, rn = gn - bn * 121;
            const float* xb = x + (size_t)bn * 221184 + 2 * (rn / 11) * 576 + 2 * (rn % 11) * 24;
            A0 = __ldg(reinterpret_cast<const float4*>(xb + so0));
            B0 = __ldg(reinterpret_cast<const float4*>(xb + so0 + 13824));
            if (h1) {
                A1 = __ldg(reinterpret_cast<const float4*>(xb + so1));
                B1 = __ldg(reinterpret_cast<const float4*>(xb + so1 + 13824));
            }
        }

        // ---- compute: streamed x from smem, weights in regs (R12 loop) ----
        const u64* xw = xs + (it & 1) * 1728 + wid * 216;
        u64 acc[11];
#pragma unroll
        for (int i = 0; i < 11; ++i) acc[i] = 0ull;

#pragma unroll
        for (int rr = 0; rr < 9; ++rr) {
            const ulonglong2* rp = reinterpret_cast<const ulonglong2*>(xw + rr * 24);
            ulonglong2 tt = rp[0];
            u64 x0 = tt.x, x1 = tt.y;
#pragma unroll
            for (int ow = 0; ow < 11; ++ow) {
                ulonglong2 tn = rp[ow + 1];
                fma2(acc[ow], wr[rr * 3 + 0], x0);
                fma2(acc[ow], wr[rr * 3 + 1], x1);
                fma2(acc[ow], wr[rr * 3 + 2], tn.x);
                x0 = tn.x;
                x1 = tn.y;
            }
        }

        // ---- write partials to this tile's red buffer ----
        float* redc = red + (it & 1) * 2816 + wid * 352;
#pragma unroll
        for (int ow = 0; ow < 11; ++ow) {
            float lo, hi;
            asm("mov.b64 {%0, %1}, %2;" : "=f"(lo), "=f"(hi) : "l"(acc[ow]));
            redc[ow * 32 + lane] = lo + hi;
        }

        // ---- stage next tile into the other xs buffer ----
        // Safe: all warps' reads of xs[(it+1)&1] (tile it-1) finished before
        // barrier(it-1), which precedes these writes.
        if (more) {
            float4* d = reinterpret_cast<float4*>(xs + ((it + 1) & 1) * 1728);
            d[df0]     = make_float4(A0.x, B0.x, A0.y, B0.y);
            d[df0 + 1] = make_float4(A0.z, B0.z, A0.w, B0.w);
            if (h1) {
                d[df1]     = make_float4(A1.x, B1.x, A1.y, B1.y);
                d[df1 + 1] = make_float4(A1.z, B1.z, A1.w, B1.w);
            }
        }

        __syncthreads();   // red[it&1] + xs[(it+1)&1] visible block-wide

        // ---- reduce + store tile it (overlaps tile it+1's compute issue) ----
        {
            const float* rb = red + (it & 1) * 2816;
            if (tid < 96) {
                int j = tid + 256;
                float s1 = cb;
#pragma unroll
                for (int w = 0; w < 8; ++w) s1 += rb[w * 352 + j];
                out[((size_t)(b * 32 + lane)) * 1331 + od * 121 + oh * 11 + (j >> 5)] = s1;
            }
            float s0 = cb;
            int j0 = (tid < 352) ? tid : 0;
#pragma unroll
            for (int w = 0; w < 8; ++w) s0 += rb[w * 352 + j0];
            if (tid < 352)
                out[((size_t)(b * 32 + lane)) * 1331 + od * 121 + oh * 11 + (tid >> 5)] = s0;
        }
        // no second barrier: red[it&1] is rewritten only at iteration it+2,
        // and barrier(it+1) separates these reads from those writes.
    }
}

extern "C" void kernel_launch(void* const* d_in, const int* in_sizes, int n_in,
                              void* d_out, int out_size) {
    const float* x     = (const float*)d_in[0];
    const float* w     = (const float*)d_in[1];
    const float* bias  = (const float*)d_in[2];
    const float* gamma = (const float*)d_in[3];
    const float* beta  = (const float*)d_in[4];
    const float* mean  = (const float*)d_in[5];
    const float* var   = (const float*)d_in[6];
    float* out = (float*)d_out;

    cudaFuncSetAttribute(conv_fused_kernel,
                         cudaFuncAttributeMaxDynamicSharedMemorySize, 50176);
    conv_fused_kernel<<<296, 256, 50176>>>(x, w, bias, gamma, beta, mean, var, out);
}